// round 10
// baseline (speedup 1.0000x reference)
#include <cuda_runtime.h>
#include <math.h>

#define BATCH   16
#define HH      512
#define WW      512
#define NPIX    (HH*WW)
#define KK      50
#define NITERS  10

#define TDIM    32            // 32x32 pixel tile per block
#define PIXPT   8             // pixels per thread (along x)
#define THREADS 128           // 32 rows * 4 threads/row; warp = 8 rows x 32 cols
#define TILES   (WW/TDIM)     // 16

// Triple-buffered segment sums: r,g,b, y*ratio, x*ratio, count
__device__ double g_sums[3][BATCH][KK][6];

__device__ __forceinline__ float ratiof() {
    // COMPACTNESS / sqrt(N/K), rounded to f32 exactly like the reference
    return (float)(10.0 / sqrt((double)NPIX / (double)KK));
}

// -------------------------------------------------------------------------
// Fused: center update (from read buffer) + assignment + segment
// accumulation (into write buffer) + zeroing of the dead buffer.
// Distance formula replicates the reference (FROZEN — zero label flips):
//   d = f2 + c2 - 2*dot   (argmin, first-index tie-break).
// Pruning: per-WARP bbox (8 rows x 32 cols) -> 64-bit candidate bitmask in
// uniform registers; ffsll iteration preserves ascending index order.
// Pixel loads issued FIRST to overlap L2 latency with the prologue.
// -------------------------------------------------------------------------
__global__ void __launch_bounds__(THREADS, 8)
k_assign(const float* __restrict__ X, int rb, int wb, int zb, int first) {
    const int img = blockIdx.z;
    const int x0  = blockIdx.x * TDIM;
    const int y0  = blockIdx.y * TDIM;
    const int t   = threadIdx.x;
    const int lane = t & 31;
    const int wrp  = t >> 5;
    const float R = ratiof();

    // ---- Pixel loads first: independent of centers, overlap the prologue
    const int ywa = y0 + 8*wrp;             // warp's first row
    const int xo  = x0 + (t & 3) * PIXPT;
    const int y   = ywa + ((t & 31) >> 2);
    size_t base = ((size_t)(img*3)*HH + y) * WW + xo;
    float4 rA = *reinterpret_cast<const float4*>(X + base);
    float4 rB = *reinterpret_cast<const float4*>(X + base + 4);
    float4 gA = *reinterpret_cast<const float4*>(X + base + (size_t)HH*WW);
    float4 gB = *reinterpret_cast<const float4*>(X + base + (size_t)HH*WW + 4);
    float4 bA = *reinterpret_cast<const float4*>(X + base + 2*(size_t)HH*WW);
    float4 bB = *reinterpret_cast<const float4*>(X + base + 2*(size_t)HH*WW + 4);

    __shared__ float sC[KK][5];
    __shared__ float sC2[KK];

    // Inline center computation; all-f32 arithmetic (no f64 divides).
    if (t < KK) {
        float c0, c1, c2, c3, c4;
        if (first) {
            int gi = t >> 3, gj = t & 7;
            int yy = 64*gi + 32, xx = 64*gj + 32;
            size_t cb = ((size_t)(img*3)*HH + yy) * WW + xx;
            c0 = X[cb];
            c1 = X[cb + (size_t)HH*WW];
            c2 = X[cb + 2*(size_t)HH*WW];
            c3 = (float)yy * R;
            c4 = (float)xx * R;
        } else {
            const double* s = &g_sums[rb][img][t][0];
            float inv = 1.0f / fmaxf((float)s[5], 1.0f);
            c0 = (float)s[0] * inv;
            c1 = (float)s[1] * inv;
            c2 = (float)s[2] * inv;
            c3 = (float)s[3] * inv;
            c4 = (float)s[4] * inv;
        }
        sC[t][0]=c0; sC[t][1]=c1; sC[t][2]=c2; sC[t][3]=c3; sC[t][4]=c4;
        sC2[t] = (((c0*c0 + c1*c1) + c2*c2) + c3*c3) + c4*c4;
    }
    // One designated block per image zeroes the dead buffer for iter it+2
    if (blockIdx.x == 0 && blockIdx.y == 0) {
        double* z = &g_sums[zb][img][0][0];
        for (int i = t; i < KK*6; i += THREADS) z[i] = 0.0;
    }
    __syncthreads();

    // Per-warp pruning over the warp's own 8-row x 32-col bbox.
    // Lane handles centers j = lane and j = lane+32; LB/UB from bbox;
    // min-UB butterfly; ballots -> one uniform 64-bit candidate mask.
    float ya = (float)ywa * R;
    float yb = (float)(ywa + 7) * R;
    float xa = (float)x0 * R;
    float xb = (float)(x0 + TDIM - 1) * R;
    float lb0, lb1;
    float ubmin = 3.0e38f;
    {
        int j = lane;
        float c3 = sC[j][3], c4 = sC[j][4];
        float dymin = fmaxf(fmaxf(ya - c3, c3 - yb), 0.0f);
        float dxmin = fmaxf(fmaxf(xa - c4, c4 - xb), 0.0f);
        float dymax = fmaxf(fabsf(ya - c3), fabsf(yb - c3));
        float dxmax = fmaxf(fabsf(xa - c4), fabsf(xb - c4));
        lb0 = dymin*dymin + dxmin*dxmin;
        ubmin = dymax*dymax + dxmax*dxmax + 3.0f;   // + color max (<=3)
    }
    {
        int j = 32 + lane;
        if (j < KK) {
            float c3 = sC[j][3], c4 = sC[j][4];
            float dymin = fmaxf(fmaxf(ya - c3, c3 - yb), 0.0f);
            float dxmin = fmaxf(fmaxf(xa - c4, c4 - xb), 0.0f);
            float dymax = fmaxf(fabsf(ya - c3), fabsf(yb - c3));
            float dxmax = fmaxf(fabsf(xa - c4), fabsf(xb - c4));
            lb1 = dymin*dymin + dxmin*dxmin;
            ubmin = fminf(ubmin, dymax*dymax + dxmax*dxmax + 3.0f);
        } else {
            lb1 = 3.0e38f;
        }
    }
    #pragma unroll
    for (int o = 16; o > 0; o >>= 1)
        ubmin = fminf(ubmin, __shfl_xor_sync(0xffffffffu, ubmin, o));
    const float thr = ubmin + 1.0f;  // slack >> fp32 rounding of distance formula
    unsigned cm0 = __ballot_sync(0xffffffffu, lb0 <= thr);
    unsigned cm1 = __ballot_sync(0xffffffffu, (32 + lane < KK) && (lb1 <= thr));
    const unsigned long long cmask =
        (unsigned long long)cm0 | ((unsigned long long)cm1 << 32);

    const float ys = (float)y * R;
    float rv[PIXPT] = {rA.x,rA.y,rA.z,rA.w, rB.x,rB.y,rB.z,rB.w};
    float gv[PIXPT] = {gA.x,gA.y,gA.z,gA.w, gB.x,gB.y,gB.z,gB.w};
    float bv[PIXPT] = {bA.x,bA.y,bA.z,bA.w, bB.x,bB.y,bB.z,bB.w};
    float xs[PIXPT], f2[PIXPT], best[PIXPT];
    int   bj[PIXPT];
    #pragma unroll
    for (int i = 0; i < PIXPT; i++) {
        xs[i]   = (float)(xo + i) * R;
        f2[i]   = (((rv[i]*rv[i] + gv[i]*gv[i]) + bv[i]*bv[i]) + ys*ys) + xs[i]*xs[i];
        best[i] = 3.0e38f;
        bj[i]   = 0;
    }

    // Mainloop over the 64-bit candidate mask (ascending j; warp-uniform).
    unsigned long long mm = cmask;
    while (mm) {
        int j = __ffsll(mm) - 1; mm &= mm - 1;
        float c0=sC[j][0], c1=sC[j][1], c2=sC[j][2], c3=sC[j][3], c4=sC[j][4];
        float cc = sC2[j];
        #pragma unroll
        for (int i = 0; i < PIXPT; i++) {
            float dot = rv[i]*c0 + gv[i]*c1 + bv[i]*c2 + ys*c3 + xs[i]*c4;
            float v = (f2[i] + cc) - 2.0f*dot;
            if (v < best[i]) { best[i] = v; bj[i] = j; }   // strict <: first index wins
        }
    }

    // Epilogue: per present candidate, 5 float butterfly chains + integer
    // REDUX for the count; lane 0 adds to global (f64 atomics).
    mm = cmask;
    while (mm) {
        int j = __ffsll(mm) - 1; mm &= mm - 1;
        float pr=0.f, pg=0.f, pb=0.f, px=0.f;
        int ipc = 0;
        #pragma unroll
        for (int i = 0; i < PIXPT; i++) {
            if (bj[i] == j) { pr+=rv[i]; pg+=gv[i]; pb+=bv[i]; px+=xs[i]; ipc++; }
        }
        unsigned pm = __ballot_sync(0xffffffffu, ipc > 0);
        if (pm == 0u) continue;           // uniform across warp
        float py = ys * (float)ipc;       // y contribution (row varies per thread)
        int cnt = __reduce_add_sync(0xffffffffu, ipc);
        #pragma unroll
        for (int o = 16; o > 0; o >>= 1) {
            pr += __shfl_down_sync(0xffffffffu, pr, o);
            pg += __shfl_down_sync(0xffffffffu, pg, o);
            pb += __shfl_down_sync(0xffffffffu, pb, o);
            py += __shfl_down_sync(0xffffffffu, py, o);
            px += __shfl_down_sync(0xffffffffu, px, o);
        }
        if (lane == 0) {
            double* gs = &g_sums[wb][img][j][0];
            atomicAdd(gs + 0, (double)pr);
            atomicAdd(gs + 1, (double)pg);
            atomicAdd(gs + 2, (double)pb);
            atomicAdd(gs + 3, (double)py);
            atomicAdd(gs + 4, (double)px);
            atomicAdd(gs + 5, (double)cnt);
        }
    }
}

// -------------------------------------------------------------------------
// Finalize: mean_rgb[c] = (1/N) * sum_seg segsum_c / max(cnt,1); then k.
// All-double. Re-zeroes buffers 1 and 2 for graph-replay self-consistency
// (buffer 0 is zeroed by the last k_assign launch).
// -------------------------------------------------------------------------
__global__ void k_final(float* __restrict__ out, int fb) {
    int img = blockIdx.x;
    int t   = threadIdx.x;
    __shared__ double sr[KK], sg[KK], sb[KK];
    if (t < KK) {
        const double* s = &g_sums[fb][img][t][0];
        double m = fmax(s[5], 1.0);
        sr[t] = s[0] / m;
        sg[t] = s[1] / m;
        sb[t] = s[2] / m;
    }
    __syncthreads();
    {   // zero buffers 1 and 2 for this image
        double* z1 = &g_sums[1][img][0][0];
        double* z2 = &g_sums[2][img][0][0];
        for (int i = t; i < KK*6; i += blockDim.x) { z1[i] = 0.0; z2[i] = 0.0; }
    }
    if (t == 0) {
        double tr=0.0, tg=0.0, tb=0.0;
        for (int j = 0; j < KK; j++) { tr += sr[j]; tg += sg[j]; tb += sb[j]; }
        const double invN = 1.0 / (double)NPIX;
        double mr = tr * invN, mg = tg * invN, mb = tb * invN;
        double Drg = (mr-mg)*(mr-mg);
        double Drb = (mr-mb)*(mr-mb);
        double Dgb = (mb-mg)*(mb-mg);
        out[img] = (float)sqrt(Drg*Drg + Drb*Drb + Dgb*Dgb);
    }
}

// -------------------------------------------------------------------------
// Launch schedule (triple buffer):
//   it reads S[it%3] (it=0: samples X), writes S[(it+1)%3], zeroes S[(it+2)%3]
//   Invariant: write buffer is always zero at launch; after k_final all
//   three buffers are zero again (graph replay safe).
// -------------------------------------------------------------------------
extern "C" void kernel_launch(void* const* d_in, const int* in_sizes, int n_in,
                              void* d_out, int out_size) {
    const float* X = (const float*)d_in[0];
    float* out = (float*)d_out;

    dim3 grid(TILES, TILES, BATCH);
    for (int it = 0; it <= NITERS; it++) {
        k_assign<<<grid, THREADS>>>(X, it % 3, (it + 1) % 3, (it + 2) % 3,
                                    it == 0 ? 1 : 0);
    }
    k_final<<<BATCH, 64>>>(out, (NITERS + 1) % 3);
}